// round 1
// baseline (speedup 1.0000x reference)
#include <cuda_runtime.h>
#include <cuda_bf16.h>
#include <cstdint>

#define N_NODES 100000
#define N_EDGES 3200000
#define EMB 32
#define NFEAT 128
#define N_ACT 1024
#define MP_ITERS 5

// ---------------- device scratch (static, no allocs) ----------------
__device__ int   g_is64;
__device__ int   g_src[N_EDGES];
__device__ int   g_dst[N_EDGES];
__device__ int   g_csr[N_EDGES];
__device__ int   g_deg[N_NODES];
__device__ int   g_rowstart[N_NODES + 1];
__device__ int   g_fill[N_NODES];
__device__ float g_x[N_NODES * EMB];
__device__ float g_m[N_NODES * EMB];
__device__ float g_part[256 * EMB];

__device__ __forceinline__ float lrelu(float v) { return v > 0.f ? v : 0.01f * v; }

// ---------------- K0: probe int32 vs int64 edge dtype ----------------
__global__ void k_probe(const void* edge) {
    const long long* p = (const long long*)edge;
    int bad = 0;
    for (int i = threadIdx.x; i < 1024; i += blockDim.x) {
        long long v = p[i];
        if (v < 0 || v >= N_NODES) bad = 1;
    }
    bad = __syncthreads_or(bad);
    if (threadIdx.x == 0) g_is64 = bad ? 0 : 1;
}

// ---------------- K1: convert edges to int32 + degree histogram ----------------
__global__ void k_convert(const void* edge) {
    int e = blockIdx.x * blockDim.x + threadIdx.x;
    if (e >= N_EDGES) return;
    int s, d;
    if (g_is64) {
        const long long* p = (const long long*)edge;
        s = (int)p[e];
        d = (int)p[N_EDGES + e];
    } else {
        const int* p = (const int*)edge;
        s = p[e];
        d = p[N_EDGES + e];
    }
    g_src[e] = s;
    g_dst[e] = d;
    atomicAdd(&g_deg[d], 1);
}

// ---------------- K2: exclusive scan of degrees (one block, fixed order) ----------------
__global__ void k_scan() {
    __shared__ int warp_sums[32];
    const int tid = threadIdx.x;
    const int lane = tid & 31, wid = tid >> 5;
    int carry = 0;
    for (int base = 0; base < N_NODES; base += 1024) {
        int i = base + tid;
        int v = (i < N_NODES) ? g_deg[i] : 0;
        int x = v;
        #pragma unroll
        for (int o = 1; o < 32; o <<= 1) {
            int t = __shfl_up_sync(0xffffffffu, x, o);
            if (lane >= o) x += t;
        }
        if (lane == 31) warp_sums[wid] = x;
        __syncthreads();
        if (tid < 32) {
            int w = warp_sums[tid];
            #pragma unroll
            for (int o = 1; o < 32; o <<= 1) {
                int t = __shfl_up_sync(0xffffffffu, w, o);
                if (tid >= o) w += t;
            }
            warp_sums[tid] = w;
        }
        __syncthreads();
        int excl = carry + x - v + (wid ? warp_sums[wid - 1] : 0);
        int total = warp_sums[31];
        if (i < N_NODES) { g_rowstart[i] = excl; g_fill[i] = excl; }
        carry += total;
        __syncthreads();
    }
    if (tid == 0) g_rowstart[N_NODES] = carry;
}

// ---------------- K3: fill CSR ----------------
__global__ void k_fill() {
    int e = blockIdx.x * blockDim.x + threadIdx.x;
    if (e >= N_EDGES) return;
    int d = g_dst[e];
    int pos = atomicAdd(&g_fill[d], 1);
    g_csr[pos] = g_src[e];
}

// ---------------- K4: embed + first message (warp per node) ----------------
__global__ __launch_bounds__(256) void k_embed(const float* __restrict__ nf,
                                               const float* __restrict__ We,
                                               const float* __restrict__ be,
                                               const float* __restrict__ Wm,
                                               const float* __restrict__ bm) {
    __shared__ float sWe[NFEAT * EMB];
    __shared__ float sWm[EMB * EMB];
    __shared__ float sbe[EMB], sbm[EMB];
    for (int i = threadIdx.x; i < NFEAT * EMB; i += 256) sWe[i] = We[i];
    for (int i = threadIdx.x; i < EMB * EMB; i += 256) sWm[i] = Wm[i];
    if (threadIdx.x < EMB) { sbe[threadIdx.x] = be[threadIdx.x]; sbm[threadIdx.x] = bm[threadIdx.x]; }
    __syncthreads();

    int gw = (blockIdx.x * 256 + threadIdx.x) >> 5;
    int lane = threadIdx.x & 31;
    if (gw >= N_NODES) return;

    const float4* row = (const float4*)(nf + (size_t)gw * NFEAT);
    float4 mine = row[lane];
    float acc = sbe[lane];
    #pragma unroll
    for (int sl = 0; sl < 32; sl++) {
        float a0 = __shfl_sync(0xffffffffu, mine.x, sl);
        float a1 = __shfl_sync(0xffffffffu, mine.y, sl);
        float a2 = __shfl_sync(0xffffffffu, mine.z, sl);
        float a3 = __shfl_sync(0xffffffffu, mine.w, sl);
        int k = sl * 4;
        acc += a0 * sWe[(k + 0) * EMB + lane];
        acc += a1 * sWe[(k + 1) * EMB + lane];
        acc += a2 * sWe[(k + 2) * EMB + lane];
        acc += a3 * sWe[(k + 3) * EMB + lane];
    }
    float x = lrelu(acc);
    g_x[gw * EMB + lane] = x;

    float macc = sbm[lane];
    #pragma unroll
    for (int k = 0; k < EMB; k++) {
        float xk = __shfl_sync(0xffffffffu, x, k);
        macc += xk * sWm[k * EMB + lane];
    }
    g_m[gw * EMB + lane] = lrelu(macc);
}

// ---------------- K5: aggregate (CSR gather-sum) + update, fused ----------------
__global__ __launch_bounds__(256) void k_aggupd(const float* __restrict__ Wu,
                                                const float* __restrict__ bu) {
    __shared__ float sWu[2 * EMB * EMB];
    __shared__ float sbu[EMB];
    for (int i = threadIdx.x; i < 2 * EMB * EMB; i += 256) sWu[i] = Wu[i];
    if (threadIdx.x < EMB) sbu[threadIdx.x] = bu[threadIdx.x];
    __syncthreads();

    int n = (blockIdx.x * 256 + threadIdx.x) >> 5;
    int lane = threadIdx.x & 31;
    if (n >= N_NODES) return;

    int beg = g_rowstart[n];
    int end = g_rowstart[n + 1];
    float acc = 0.f;
    for (int base = beg; base < end; base += 32) {
        int idx = (base + lane < end) ? g_csr[base + lane] : 0;
        int cnt = min(32, end - base);
        for (int j = 0; j < cnt; j++) {
            int s = __shfl_sync(0xffffffffu, idx, j);
            acc += g_m[s * EMB + lane];
        }
    }

    float xo = g_x[n * EMB + lane];
    float out = sbu[lane];
    #pragma unroll
    for (int k = 0; k < EMB; k++) {
        float xk = __shfl_sync(0xffffffffu, xo, k);
        float ak = __shfl_sync(0xffffffffu, acc, k);
        out += xk * sWu[k * EMB + lane] + ak * sWu[(EMB + k) * EMB + lane];
    }
    g_x[n * EMB + lane] = lrelu(out);
}

// ---------------- K6: recompute per-node messages ----------------
__global__ __launch_bounds__(256) void k_msg(const float* __restrict__ Wm,
                                             const float* __restrict__ bm) {
    __shared__ float sWm[EMB * EMB];
    __shared__ float sbm[EMB];
    for (int i = threadIdx.x; i < EMB * EMB; i += 256) sWm[i] = Wm[i];
    if (threadIdx.x < EMB) sbm[threadIdx.x] = bm[threadIdx.x];
    __syncthreads();

    int n = (blockIdx.x * 256 + threadIdx.x) >> 5;
    int lane = threadIdx.x & 31;
    if (n >= N_NODES) return;

    float x = g_x[n * EMB + lane];
    float macc = sbm[lane];
    #pragma unroll
    for (int k = 0; k < EMB; k++) {
        float xk = __shfl_sync(0xffffffffu, x, k);
        macc += xk * sWm[k * EMB + lane];
    }
    g_m[n * EMB + lane] = lrelu(macc);
}

// ---------------- K7: partial column sums for mean (deterministic) ----------------
__global__ __launch_bounds__(256) void k_partial() {
    __shared__ float red[8][EMB];
    int lane = threadIdx.x & 31;
    int w = threadIdx.x >> 5;
    float s = 0.f;
    for (int n = blockIdx.x * 8 + w; n < N_NODES; n += 256 * 8)
        s += g_x[n * EMB + lane];
    red[w][lane] = s;
    __syncthreads();
    if (w == 0) {
        float t = red[0][lane];
        #pragma unroll
        for (int i = 1; i < 8; i++) t += red[i][lane];
        g_part[blockIdx.x * EMB + lane] = t;
    }
}

// ---------------- K8: value + actionable logits + softmax ----------------
__global__ __launch_bounds__(1024) void k_final(const void* __restrict__ act,
                                                const float* __restrict__ Wv,
                                                const float* __restrict__ bv,
                                                const float* __restrict__ Wp,
                                                const float* __restrict__ bp,
                                                float* __restrict__ out) {
    __shared__ float sh[1024];
    __shared__ float xg[EMB];
    int tid = threadIdx.x;

    if (tid < EMB) {
        float s = 0.f;
        for (int p = 0; p < 256; p++) s += g_part[p * EMB + tid];
        xg[tid] = s / (float)N_NODES;
    }
    __syncthreads();
    if (tid == 0) {
        float v = bv[0];
        #pragma unroll
        for (int k = 0; k < EMB; k++) v += xg[k] * Wv[k];
        out[0] = v;
    }

    int node;
    if (g_is64) node = (int)((const long long*)act)[tid];
    else        node = ((const int*)act)[tid];

    float l = bp[0];
    #pragma unroll
    for (int k = 0; k < EMB; k++) l += g_x[node * EMB + k] * Wp[k];

    sh[tid] = l;
    __syncthreads();
    for (int s2 = 512; s2 > 0; s2 >>= 1) {
        if (tid < s2) sh[tid] = fmaxf(sh[tid], sh[tid + s2]);
        __syncthreads();
    }
    float mx = sh[0];
    __syncthreads();
    float e = expf(l - mx);
    sh[tid] = e;
    __syncthreads();
    for (int s2 = 512; s2 > 0; s2 >>= 1) {
        if (tid < s2) sh[tid] += sh[tid + s2];
        __syncthreads();
    }
    out[1 + tid] = e / sh[0];
}

// ---------------- launch ----------------
extern "C" void kernel_launch(void* const* d_in, const int* in_sizes, int n_in,
                              void* d_out, int out_size) {
    const float* node_feats = (const float*)d_in[0];
    const void*  edge_index = d_in[1];
    const void*  actionable = d_in[2];
    const float* W_embed = (const float*)d_in[3];
    const float* b_embed = (const float*)d_in[4];
    const float* W_msg   = (const float*)d_in[5];
    const float* b_msg   = (const float*)d_in[6];
    const float* W_upd   = (const float*)d_in[7];
    const float* b_upd   = (const float*)d_in[8];
    const float* W_val   = (const float*)d_in[9];
    const float* b_val   = (const float*)d_in[10];
    const float* W_pol   = (const float*)d_in[11];
    const float* b_pol   = (const float*)d_in[12];
    float* out = (float*)d_out;

    void* deg_ptr = nullptr;
    cudaGetSymbolAddress(&deg_ptr, g_deg);
    cudaMemsetAsync(deg_ptr, 0, N_NODES * sizeof(int));

    const int EB = (N_EDGES + 255) / 256;     // 12500
    const int NB = (N_NODES * 32 + 255) / 256; // warp per node -> 12500 blocks

    k_probe<<<1, 256>>>(edge_index);
    k_convert<<<EB, 256>>>(edge_index);
    k_scan<<<1, 1024>>>();
    k_fill<<<EB, 256>>>();
    k_embed<<<NB, 256>>>(node_feats, W_embed, b_embed, W_msg, b_msg);

    for (int it = 0; it < MP_ITERS; it++) {
        k_aggupd<<<NB, 256>>>(W_upd, b_upd);
        if (it != MP_ITERS - 1)
            k_msg<<<NB, 256>>>(W_msg, b_msg);
    }

    k_partial<<<256, 256>>>();
    k_final<<<1, 1024>>>(actionable, W_val, b_val, W_pol, b_pol, out);
}

// round 2
// speedup vs baseline: 1.2296x; 1.2296x over previous
#include <cuda_runtime.h>
#include <cuda_bf16.h>
#include <cstdint>

#define N_NODES 100000
#define N_EDGES 3200000
#define EMB 32
#define NFEAT 128
#define N_ACT 1024
#define MP_ITERS 5
#define FULL 0xffffffffu

// ---------------- device scratch (static, no allocs) ----------------
__device__ int   g_is64;
__device__ int   g_csr[N_EDGES];
__device__ int   g_deg[N_NODES];
__device__ int   g_rowstart[N_NODES + 1];
__device__ int   g_fill[N_NODES];
__device__ float g_x[N_NODES * EMB];
__device__ float g_m[2][N_NODES * EMB];
__device__ float g_part[256 * EMB];

__device__ __forceinline__ float lrelu(float v) { return v > 0.f ? v : 0.01f * v; }
__device__ __forceinline__ float4 lrelu4(float4 v) {
    return make_float4(lrelu(v.x), lrelu(v.y), lrelu(v.z), lrelu(v.w));
}
__device__ __forceinline__ void add4(float4& a, const float4& b) {
    a.x += b.x; a.y += b.y; a.z += b.z; a.w += b.w;
}
__device__ __forceinline__ void xorred4(float4& a) {
    a.x += __shfl_xor_sync(FULL, a.x, 8);
    a.y += __shfl_xor_sync(FULL, a.y, 8);
    a.z += __shfl_xor_sync(FULL, a.z, 8);
    a.w += __shfl_xor_sync(FULL, a.w, 8);
    a.x += __shfl_xor_sync(FULL, a.x, 16);
    a.y += __shfl_xor_sync(FULL, a.y, 16);
    a.z += __shfl_xor_sync(FULL, a.z, 16);
    a.w += __shfl_xor_sync(FULL, a.w, 16);
}
#define PICK4(v, c) ((c) == 0 ? (v).x : (c) == 1 ? (v).y : (c) == 2 ? (v).z : (v).w)

// ---------------- K0: probe int32 vs int64 edge dtype ----------------
__global__ void k_probe(const void* edge) {
    const long long* p = (const long long*)edge;
    int bad = 0;
    for (int i = threadIdx.x; i < 1024; i += blockDim.x) {
        long long v = p[i];
        if (v < 0 || v >= N_NODES) bad = 1;
    }
    bad = __syncthreads_or(bad);
    if (threadIdx.x == 0) g_is64 = bad ? 0 : 1;
}

// ---------------- K1: degree histogram ----------------
__global__ void k_convert(const void* edge) {
    int e = blockIdx.x * blockDim.x + threadIdx.x;
    if (e >= N_EDGES) return;
    int d;
    if (g_is64) d = (int)((const long long*)edge)[N_EDGES + e];
    else        d = ((const int*)edge)[N_EDGES + e];
    atomicAdd(&g_deg[d], 1);
}

// ---------------- K2: exclusive scan of degrees (one block) ----------------
__global__ void k_scan() {
    __shared__ int warp_sums[32];
    const int tid = threadIdx.x;
    const int lane = tid & 31, wid = tid >> 5;
    int carry = 0;
    for (int base = 0; base < N_NODES; base += 1024) {
        int i = base + tid;
        int v = (i < N_NODES) ? g_deg[i] : 0;
        int x = v;
        #pragma unroll
        for (int o = 1; o < 32; o <<= 1) {
            int t = __shfl_up_sync(FULL, x, o);
            if (lane >= o) x += t;
        }
        if (lane == 31) warp_sums[wid] = x;
        __syncthreads();
        if (tid < 32) {
            int w = warp_sums[tid];
            #pragma unroll
            for (int o = 1; o < 32; o <<= 1) {
                int t = __shfl_up_sync(FULL, w, o);
                if (tid >= o) w += t;
            }
            warp_sums[tid] = w;
        }
        __syncthreads();
        int excl = carry + x - v + (wid ? warp_sums[wid - 1] : 0);
        int total = warp_sums[31];
        if (i < N_NODES) { g_rowstart[i] = excl; g_fill[i] = excl; }
        carry += total;
        __syncthreads();
    }
    if (tid == 0) g_rowstart[N_NODES] = carry;
}

// ---------------- K3: fill CSR ----------------
__global__ void k_fill(const void* edge) {
    int e = blockIdx.x * blockDim.x + threadIdx.x;
    if (e >= N_EDGES) return;
    int s, d;
    if (g_is64) {
        const long long* p = (const long long*)edge;
        s = (int)p[e];
        d = (int)p[N_EDGES + e];
    } else {
        const int* p = (const int*)edge;
        s = p[e];
        d = p[N_EDGES + e];
    }
    int pos = atomicAdd(&g_fill[d], 1);
    g_csr[pos] = s;
}

// ---------------- K4: embed + first message (warp per node) ----------------
__global__ __launch_bounds__(256) void k_embed(const float* __restrict__ nf,
                                               const float* __restrict__ We,
                                               const float* __restrict__ be,
                                               const float* __restrict__ Wm,
                                               const float* __restrict__ bm) {
    __shared__ float sWe[NFEAT * EMB];
    __shared__ float sWm[EMB * EMB];
    __shared__ float sbe[EMB], sbm[EMB];
    for (int i = threadIdx.x; i < NFEAT * EMB; i += 256) sWe[i] = We[i];
    for (int i = threadIdx.x; i < EMB * EMB; i += 256) sWm[i] = Wm[i];
    if (threadIdx.x < EMB) { sbe[threadIdx.x] = be[threadIdx.x]; sbm[threadIdx.x] = bm[threadIdx.x]; }
    __syncthreads();

    int gw = (blockIdx.x * 256 + threadIdx.x) >> 5;
    int lane = threadIdx.x & 31;
    if (gw >= N_NODES) return;

    const float4* row = (const float4*)(nf + (size_t)gw * NFEAT);
    float4 mine = row[lane];
    float acc = sbe[lane];
    #pragma unroll
    for (int sl = 0; sl < 32; sl++) {
        float a0 = __shfl_sync(FULL, mine.x, sl);
        float a1 = __shfl_sync(FULL, mine.y, sl);
        float a2 = __shfl_sync(FULL, mine.z, sl);
        float a3 = __shfl_sync(FULL, mine.w, sl);
        int k = sl * 4;
        acc += a0 * sWe[(k + 0) * EMB + lane];
        acc += a1 * sWe[(k + 1) * EMB + lane];
        acc += a2 * sWe[(k + 2) * EMB + lane];
        acc += a3 * sWe[(k + 3) * EMB + lane];
    }
    float x = lrelu(acc);
    g_x[gw * EMB + lane] = x;

    float macc = sbm[lane];
    #pragma unroll
    for (int k = 0; k < EMB; k++) {
        float xk = __shfl_sync(FULL, x, k);
        macc += xk * sWm[k * EMB + lane];
    }
    g_m[0][gw * EMB + lane] = lrelu(macc);
}

// ---------------- K5: aggregate + update + next message, fused ----------------
// warp per node; 8-lane groups, float4 per lane (features 4*sub .. 4*sub+3)
__global__ __launch_bounds__(256) void k_aggupd(const float* __restrict__ Wu,
                                                const float* __restrict__ bu,
                                                const float* __restrict__ Wm,
                                                const float* __restrict__ bm,
                                                int pin, int last) {
    __shared__ float4 sWu[2 * EMB * 8];   // [64 rows][8 float4]
    __shared__ float4 sWm[EMB * 8];       // [32 rows][8 float4]
    __shared__ float4 sbu[8], sbm[8];
    for (int i = threadIdx.x; i < 2 * EMB * 8; i += 256) sWu[i] = ((const float4*)Wu)[i];
    for (int i = threadIdx.x; i < EMB * 8; i += 256) sWm[i] = ((const float4*)Wm)[i];
    if (threadIdx.x < 8)  sbu[threadIdx.x] = ((const float4*)bu)[threadIdx.x];
    else if (threadIdx.x < 16) sbm[threadIdx.x - 8] = ((const float4*)bm)[threadIdx.x - 8];
    __syncthreads();

    const int n = (blockIdx.x * 256 + threadIdx.x) >> 5;
    const int lane = threadIdx.x & 31;
    const int g = lane >> 3;         // group 0..3
    const int sub = lane & 7;        // float4 index within row
    if (n >= N_NODES) return;

    const float* __restrict__ mbuf = g_m[pin];
    float* __restrict__ mout = g_m[pin ^ 1];

    const int beg = g_rowstart[n];
    const int end = g_rowstart[n + 1];

    // ---- gather-sum of messages: 8 edges per loop trip, 8 float4 LDGs in flight
    float4 acc0 = make_float4(0.f, 0.f, 0.f, 0.f);
    float4 acc1 = make_float4(0.f, 0.f, 0.f, 0.f);
    for (int base = beg; base < end; base += 8) {
        int e0 = base + g;
        int e1 = e0 + 4;
        if (e0 < end) {
            int i0 = g_csr[e0];
            add4(acc0, ((const float4*)(mbuf + i0 * EMB))[sub]);
        }
        if (e1 < end) {
            int i1 = g_csr[e1];
            add4(acc1, ((const float4*)(mbuf + i1 * EMB))[sub]);
        }
    }
    add4(acc0, acc1);
    xorred4(acc0);   // every lane now holds full agg for features [4*sub, 4*sub+3]

    // ---- update GEMM: out[f] = sum_k x[k]*Wu[k][f] + agg[k]*Wu[32+k][f]
    const float xown = g_x[n * EMB + lane];   // x feature `lane`
    float4 outv = make_float4(0.f, 0.f, 0.f, 0.f);
    #pragma unroll
    for (int j = 0; j < 8; j++) {
        const int k = (lane & 24) + j;                    // group handles k in [8g, 8g+8)
        const float xk = __shfl_sync(FULL, xown, k);
        const int s = ((lane & 24) >> 2) + (j >> 2);      // lane holding agg[k]
        const float ac = PICK4(acc0, j & 3);
        const float ak = __shfl_sync(FULL, ac, s);
        const float4 w1 = sWu[k * 8 + sub];
        const float4 w2 = sWu[(k + EMB) * 8 + sub];
        outv.x += xk * w1.x + ak * w2.x;
        outv.y += xk * w1.y + ak * w2.y;
        outv.z += xk * w1.z + ak * w2.z;
        outv.w += xk * w1.w + ak * w2.w;
    }
    xorred4(outv);
    {
        const float4 b = sbu[sub];
        outv.x += b.x; outv.y += b.y; outv.z += b.z; outv.w += b.w;
        outv = lrelu4(outv);
    }
    if (lane < 8) ((float4*)(g_x + n * EMB))[lane] = outv;

    // ---- fused next-iteration message: m = lrelu(x_new @ Wm + bm)
    if (!last) {
        float4 macc = make_float4(0.f, 0.f, 0.f, 0.f);
        #pragma unroll
        for (int j = 0; j < 8; j++) {
            const int k = (lane & 24) + j;
            const int s = ((lane & 24) >> 2) + (j >> 2);
            const float xc = PICK4(outv, j & 3);
            const float xk = __shfl_sync(FULL, xc, s);
            const float4 w = sWm[k * 8 + sub];
            macc.x += xk * w.x;
            macc.y += xk * w.y;
            macc.z += xk * w.z;
            macc.w += xk * w.w;
        }
        xorred4(macc);
        const float4 b = sbm[sub];
        macc.x += b.x; macc.y += b.y; macc.z += b.z; macc.w += b.w;
        macc = lrelu4(macc);
        if (lane < 8) ((float4*)(mout + n * EMB))[lane] = macc;
    }
}

// ---------------- K7: partial column sums for mean (deterministic) ----------------
__global__ __launch_bounds__(256) void k_partial() {
    __shared__ float red[8][EMB];
    int lane = threadIdx.x & 31;
    int w = threadIdx.x >> 5;
    float s = 0.f;
    for (int n = blockIdx.x * 8 + w; n < N_NODES; n += 256 * 8)
        s += g_x[n * EMB + lane];
    red[w][lane] = s;
    __syncthreads();
    if (w == 0) {
        float t = red[0][lane];
        #pragma unroll
        for (int i = 1; i < 8; i++) t += red[i][lane];
        g_part[blockIdx.x * EMB + lane] = t;
    }
}

// ---------------- K8: value + actionable logits + softmax ----------------
__global__ __launch_bounds__(1024) void k_final(const void* __restrict__ act,
                                                const float* __restrict__ Wv,
                                                const float* __restrict__ bv,
                                                const float* __restrict__ Wp,
                                                const float* __restrict__ bp,
                                                float* __restrict__ out) {
    __shared__ float sh[1024];
    __shared__ float xg[EMB];
    int tid = threadIdx.x;

    if (tid < EMB) {
        float s = 0.f;
        for (int p = 0; p < 256; p++) s += g_part[p * EMB + tid];
        xg[tid] = s / (float)N_NODES;
    }
    __syncthreads();
    if (tid == 0) {
        float v = bv[0];
        #pragma unroll
        for (int k = 0; k < EMB; k++) v += xg[k] * Wv[k];
        out[0] = v;
    }

    int node;
    if (g_is64) node = (int)((const long long*)act)[tid];
    else        node = ((const int*)act)[tid];

    float l = bp[0];
    #pragma unroll
    for (int k = 0; k < EMB; k++) l += g_x[node * EMB + k] * Wp[k];

    sh[tid] = l;
    __syncthreads();
    for (int s2 = 512; s2 > 0; s2 >>= 1) {
        if (tid < s2) sh[tid] = fmaxf(sh[tid], sh[tid + s2]);
        __syncthreads();
    }
    float mx = sh[0];
    __syncthreads();
    float e = expf(l - mx);
    sh[tid] = e;
    __syncthreads();
    for (int s2 = 512; s2 > 0; s2 >>= 1) {
        if (tid < s2) sh[tid] += sh[tid + s2];
        __syncthreads();
    }
    out[1 + tid] = e / sh[0];
}

// ---------------- launch ----------------
extern "C" void kernel_launch(void* const* d_in, const int* in_sizes, int n_in,
                              void* d_out, int out_size) {
    const float* node_feats = (const float*)d_in[0];
    const void*  edge_index = d_in[1];
    const void*  actionable = d_in[2];
    const float* W_embed = (const float*)d_in[3];
    const float* b_embed = (const float*)d_in[4];
    const float* W_msg   = (const float*)d_in[5];
    const float* b_msg   = (const float*)d_in[6];
    const float* W_upd   = (const float*)d_in[7];
    const float* b_upd   = (const float*)d_in[8];
    const float* W_val   = (const float*)d_in[9];
    const float* b_val   = (const float*)d_in[10];
    const float* W_pol   = (const float*)d_in[11];
    const float* b_pol   = (const float*)d_in[12];
    float* out = (float*)d_out;

    void* deg_ptr = nullptr;
    cudaGetSymbolAddress(&deg_ptr, g_deg);
    cudaMemsetAsync(deg_ptr, 0, N_NODES * sizeof(int));

    const int EB = (N_EDGES + 255) / 256;      // 12500
    const int NB = (N_NODES * 32 + 255) / 256; // warp per node -> 12500 blocks

    k_probe<<<1, 256>>>(edge_index);
    k_convert<<<EB, 256>>>(edge_index);
    k_scan<<<1, 1024>>>();
    k_fill<<<EB, 256>>>(edge_index);
    k_embed<<<NB, 256>>>(node_feats, W_embed, b_embed, W_msg, b_msg);

    for (int it = 0; it < MP_ITERS; it++) {
        k_aggupd<<<NB, 256>>>(W_upd, b_upd, W_msg, b_msg,
                              it & 1, it == MP_ITERS - 1 ? 1 : 0);
    }

    k_partial<<<256, 256>>>();
    k_final<<<1, 1024>>>(actionable, W_val, b_val, W_pol, b_pol, out);
}

// round 3
// speedup vs baseline: 1.2306x; 1.0008x over previous
#include <cuda_runtime.h>
#include <cuda_bf16.h>
#include <cstdint>

#define N_NODES 100000
#define N_EDGES 3200000
#define EMB 32
#define NFEAT 128
#define N_ACT 1024
#define MP_ITERS 5
#define FULL 0xffffffffu
#define PBLOCKS 1216   // 8 blocks per SM on 152-SM GB300

// ---------------- device scratch (static, no allocs) ----------------
__device__ int   g_is64;
__device__ int   g_csr[N_EDGES];
__device__ int   g_deg[N_NODES];
__device__ int   g_rowstart[N_NODES + 1];
__device__ int   g_fill[N_NODES];
__device__ float g_x[N_NODES * EMB];
__device__ float g_m[2][N_NODES * EMB];
__device__ float g_part[256 * EMB];

__device__ __forceinline__ float lrelu(float v) { return v > 0.f ? v : 0.01f * v; }
__device__ __forceinline__ float4 lrelu4(float4 v) {
    return make_float4(lrelu(v.x), lrelu(v.y), lrelu(v.z), lrelu(v.w));
}
__device__ __forceinline__ void add4(float4& a, const float4& b) {
    a.x += b.x; a.y += b.y; a.z += b.z; a.w += b.w;
}
__device__ __forceinline__ void xorred4(float4& a) {
    a.x += __shfl_xor_sync(FULL, a.x, 8);
    a.y += __shfl_xor_sync(FULL, a.y, 8);
    a.z += __shfl_xor_sync(FULL, a.z, 8);
    a.w += __shfl_xor_sync(FULL, a.w, 8);
    a.x += __shfl_xor_sync(FULL, a.x, 16);
    a.y += __shfl_xor_sync(FULL, a.y, 16);
    a.z += __shfl_xor_sync(FULL, a.z, 16);
    a.w += __shfl_xor_sync(FULL, a.w, 16);
}
#define PICK4(v, c) ((c) == 0 ? (v).x : (c) == 1 ? (v).y : (c) == 2 ? (v).z : (v).w)

// ---------------- K_init: zero deg + probe dtype + embed + first message ----------------
__global__ __launch_bounds__(256) void k_init(const void* __restrict__ edge,
                                              const float* __restrict__ nf,
                                              const float* __restrict__ We,
                                              const float* __restrict__ be,
                                              const float* __restrict__ Wm,
                                              const float* __restrict__ bm) {
    // zero degree array (grid-stride)
    for (int i = blockIdx.x * 256 + threadIdx.x; i < N_NODES; i += gridDim.x * 256)
        g_deg[i] = 0;

    // block 0 probes edge dtype (int32 vs int64)
    if (blockIdx.x == 0) {
        const long long* p = (const long long*)edge;
        int bad = 0;
        for (int i = threadIdx.x; i < 1024; i += 256) {
            long long v = p[i];
            if (v < 0 || v >= N_NODES) bad = 1;
        }
        bad = __syncthreads_or(bad);
        if (threadIdx.x == 0) g_is64 = bad ? 0 : 1;
    }

    // embed weights to smem
    __shared__ float sWe[NFEAT * EMB];
    __shared__ float sWm[EMB * EMB];
    __shared__ float sbe[EMB], sbm[EMB];
    for (int i = threadIdx.x; i < NFEAT * EMB; i += 256) sWe[i] = We[i];
    for (int i = threadIdx.x; i < EMB * EMB; i += 256) sWm[i] = Wm[i];
    if (threadIdx.x < EMB) { sbe[threadIdx.x] = be[threadIdx.x]; sbm[threadIdx.x] = bm[threadIdx.x]; }
    __syncthreads();

    const int lane = threadIdx.x & 31;
    const int warps = gridDim.x * 8;
    for (int n = (blockIdx.x * 256 + threadIdx.x) >> 5; n < N_NODES; n += warps) {
        const float4* row = (const float4*)(nf + (size_t)n * NFEAT);
        float4 mine = row[lane];
        float acc = sbe[lane];
        #pragma unroll
        for (int sl = 0; sl < 32; sl++) {
            float a0 = __shfl_sync(FULL, mine.x, sl);
            float a1 = __shfl_sync(FULL, mine.y, sl);
            float a2 = __shfl_sync(FULL, mine.z, sl);
            float a3 = __shfl_sync(FULL, mine.w, sl);
            int k = sl * 4;
            acc += a0 * sWe[(k + 0) * EMB + lane];
            acc += a1 * sWe[(k + 1) * EMB + lane];
            acc += a2 * sWe[(k + 2) * EMB + lane];
            acc += a3 * sWe[(k + 3) * EMB + lane];
        }
        float x = lrelu(acc);
        g_x[n * EMB + lane] = x;

        float macc = sbm[lane];
        #pragma unroll
        for (int k = 0; k < EMB; k++) {
            float xk = __shfl_sync(FULL, x, k);
            macc += xk * sWm[k * EMB + lane];
        }
        g_m[0][n * EMB + lane] = lrelu(macc);
    }
}

// ---------------- K1: degree histogram ----------------
__global__ void k_convert(const void* edge) {
    int e = blockIdx.x * blockDim.x + threadIdx.x;
    if (e >= N_EDGES) return;
    int d;
    if (g_is64) d = (int)((const long long*)edge)[N_EDGES + e];
    else        d = ((const int*)edge)[N_EDGES + e];
    atomicAdd(&g_deg[d], 1);
}

// ---------------- K2: exclusive scan of degrees (one block) ----------------
__global__ void k_scan() {
    __shared__ int warp_sums[32];
    const int tid = threadIdx.x;
    const int lane = tid & 31, wid = tid >> 5;
    int carry = 0;
    for (int base = 0; base < N_NODES; base += 1024) {
        int i = base + tid;
        int v = (i < N_NODES) ? g_deg[i] : 0;
        int x = v;
        #pragma unroll
        for (int o = 1; o < 32; o <<= 1) {
            int t = __shfl_up_sync(FULL, x, o);
            if (lane >= o) x += t;
        }
        if (lane == 31) warp_sums[wid] = x;
        __syncthreads();
        if (tid < 32) {
            int w = warp_sums[tid];
            #pragma unroll
            for (int o = 1; o < 32; o <<= 1) {
                int t = __shfl_up_sync(FULL, w, o);
                if (tid >= o) w += t;
            }
            warp_sums[tid] = w;
        }
        __syncthreads();
        int excl = carry + x - v + (wid ? warp_sums[wid - 1] : 0);
        int total = warp_sums[31];
        if (i < N_NODES) { g_rowstart[i] = excl; g_fill[i] = excl; }
        carry += total;
        __syncthreads();
    }
    if (tid == 0) g_rowstart[N_NODES] = carry;
}

// ---------------- K3: fill CSR ----------------
__global__ void k_fill(const void* edge) {
    int e = blockIdx.x * blockDim.x + threadIdx.x;
    if (e >= N_EDGES) return;
    int s, d;
    if (g_is64) {
        const long long* p = (const long long*)edge;
        s = (int)p[e];
        d = (int)p[N_EDGES + e];
    } else {
        const int* p = (const int*)edge;
        s = p[e];
        d = p[N_EDGES + e];
    }
    int pos = atomicAdd(&g_fill[d], 1);
    g_csr[pos] = s;
}

// ---------------- K5: aggregate + update + next message, fused, persistent ----------------
// warp per node (grid-stride); 8-lane groups, float4 per lane
__global__ __launch_bounds__(256) void k_aggupd(const float* __restrict__ Wu,
                                                const float* __restrict__ bu,
                                                const float* __restrict__ Wm,
                                                const float* __restrict__ bm,
                                                int pin, int last) {
    __shared__ float4 sWu[2 * EMB * 8];   // [64 rows][8 float4]
    __shared__ float4 sWm[EMB * 8];       // [32 rows][8 float4]
    __shared__ float4 sbu[8], sbm[8];
    for (int i = threadIdx.x; i < 2 * EMB * 8; i += 256) sWu[i] = ((const float4*)Wu)[i];
    for (int i = threadIdx.x; i < EMB * 8; i += 256) sWm[i] = ((const float4*)Wm)[i];
    if (threadIdx.x < 8)  sbu[threadIdx.x] = ((const float4*)bu)[threadIdx.x];
    else if (threadIdx.x < 16) sbm[threadIdx.x - 8] = ((const float4*)bm)[threadIdx.x - 8];
    __syncthreads();

    const int lane = threadIdx.x & 31;
    const int g = lane >> 3;         // group 0..3
    const int sub = lane & 7;        // float4 index within row
    const int warps = gridDim.x * 8;

    const float4* __restrict__ mbuf = (const float4*)g_m[pin];
    float4* __restrict__ mout = (float4*)g_m[pin ^ 1];

    for (int n = (blockIdx.x * 256 + threadIdx.x) >> 5; n < N_NODES; n += warps) {
        const int beg = g_rowstart[n];
        const int end = g_rowstart[n + 1];

        // ---- gather-sum of messages: 16 edges/trip, 4 independent accumulators
        float4 a0 = make_float4(0.f, 0.f, 0.f, 0.f);
        float4 a1 = make_float4(0.f, 0.f, 0.f, 0.f);
        float4 a2 = make_float4(0.f, 0.f, 0.f, 0.f);
        float4 a3 = make_float4(0.f, 0.f, 0.f, 0.f);
        for (int base = beg; base < end; base += 16) {
            const int e = base + g;
            int i0 = (e      < end) ? g_csr[e]      : -1;
            int i1 = (e + 4  < end) ? g_csr[e + 4]  : -1;
            int i2 = (e + 8  < end) ? g_csr[e + 8]  : -1;
            int i3 = (e + 12 < end) ? g_csr[e + 12] : -1;
            if (i0 >= 0) add4(a0, mbuf[i0 * 8 + sub]);
            if (i1 >= 0) add4(a1, mbuf[i1 * 8 + sub]);
            if (i2 >= 0) add4(a2, mbuf[i2 * 8 + sub]);
            if (i3 >= 0) add4(a3, mbuf[i3 * 8 + sub]);
        }
        add4(a0, a1); add4(a2, a3); add4(a0, a2);
        xorred4(a0);   // every lane holds full agg for features [4*sub, 4*sub+3]

        // ---- update GEMM: out[f] = sum_k x[k]*Wu[k][f] + agg[k]*Wu[32+k][f]
        const float xown = g_x[n * EMB + lane];
        float4 outv = make_float4(0.f, 0.f, 0.f, 0.f);
        #pragma unroll
        for (int j = 0; j < 8; j++) {
            const int k = (lane & 24) + j;
            const float xk = __shfl_sync(FULL, xown, k);
            const int s = ((lane & 24) >> 2) + (j >> 2);
            const float ac = PICK4(a0, j & 3);
            const float ak = __shfl_sync(FULL, ac, s);
            const float4 w1 = sWu[k * 8 + sub];
            const float4 w2 = sWu[(k + EMB) * 8 + sub];
            outv.x += xk * w1.x + ak * w2.x;
            outv.y += xk * w1.y + ak * w2.y;
            outv.z += xk * w1.z + ak * w2.z;
            outv.w += xk * w1.w + ak * w2.w;
        }
        xorred4(outv);
        {
            const float4 b = sbu[sub];
            outv.x += b.x; outv.y += b.y; outv.z += b.z; outv.w += b.w;
            outv = lrelu4(outv);
        }
        if (lane < 8) ((float4*)(g_x + n * EMB))[lane] = outv;

        // ---- fused next-iteration message: m = lrelu(x_new @ Wm + bm)
        if (!last) {
            float4 macc = make_float4(0.f, 0.f, 0.f, 0.f);
            #pragma unroll
            for (int j = 0; j < 8; j++) {
                const int k = (lane & 24) + j;
                const int s = ((lane & 24) >> 2) + (j >> 2);
                const float xc = PICK4(outv, j & 3);
                const float xk = __shfl_sync(FULL, xc, s);
                const float4 w = sWm[k * 8 + sub];
                macc.x += xk * w.x;
                macc.y += xk * w.y;
                macc.z += xk * w.z;
                macc.w += xk * w.w;
            }
            xorred4(macc);
            const float4 b = sbm[sub];
            macc.x += b.x; macc.y += b.y; macc.z += b.z; macc.w += b.w;
            macc = lrelu4(macc);
            if (lane < 8) mout[n * 8 + lane] = macc;
        }
    }
}

// ---------------- K7: partial column sums for mean (deterministic) ----------------
__global__ __launch_bounds__(256) void k_partial() {
    __shared__ float red[8][EMB];
    int lane = threadIdx.x & 31;
    int w = threadIdx.x >> 5;
    float s = 0.f;
    for (int n = blockIdx.x * 8 + w; n < N_NODES; n += 256 * 8)
        s += g_x[n * EMB + lane];
    red[w][lane] = s;
    __syncthreads();
    if (w == 0) {
        float t = red[0][lane];
        #pragma unroll
        for (int i = 1; i < 8; i++) t += red[i][lane];
        g_part[blockIdx.x * EMB + lane] = t;
    }
}

// ---------------- K8: value + actionable logits + softmax ----------------
__global__ __launch_bounds__(1024) void k_final(const void* __restrict__ act,
                                                const float* __restrict__ Wv,
                                                const float* __restrict__ bv,
                                                const float* __restrict__ Wp,
                                                const float* __restrict__ bp,
                                                float* __restrict__ out) {
    __shared__ float sh[1024];
    __shared__ float xg[EMB];
    int tid = threadIdx.x;

    if (tid < EMB) {
        float s = 0.f;
        for (int p = 0; p < 256; p++) s += g_part[p * EMB + tid];
        xg[tid] = s / (float)N_NODES;
    }
    __syncthreads();
    if (tid == 0) {
        float v = bv[0];
        #pragma unroll
        for (int k = 0; k < EMB; k++) v += xg[k] * Wv[k];
        out[0] = v;
    }

    int node;
    if (g_is64) node = (int)((const long long*)act)[tid];
    else        node = ((const int*)act)[tid];

    float l = bp[0];
    #pragma unroll
    for (int k = 0; k < EMB; k++) l += g_x[node * EMB + k] * Wp[k];

    sh[tid] = l;
    __syncthreads();
    for (int s2 = 512; s2 > 0; s2 >>= 1) {
        if (tid < s2) sh[tid] = fmaxf(sh[tid], sh[tid + s2]);
        __syncthreads();
    }
    float mx = sh[0];
    __syncthreads();
    float e = expf(l - mx);
    sh[tid] = e;
    __syncthreads();
    for (int s2 = 512; s2 > 0; s2 >>= 1) {
        if (tid < s2) sh[tid] += sh[tid + s2];
        __syncthreads();
    }
    out[1 + tid] = e / sh[0];
}

// ---------------- launch ----------------
extern "C" void kernel_launch(void* const* d_in, const int* in_sizes, int n_in,
                              void* d_out, int out_size) {
    const float* node_feats = (const float*)d_in[0];
    const void*  edge_index = d_in[1];
    const void*  actionable = d_in[2];
    const float* W_embed = (const float*)d_in[3];
    const float* b_embed = (const float*)d_in[4];
    const float* W_msg   = (const float*)d_in[5];
    const float* b_msg   = (const float*)d_in[6];
    const float* W_upd   = (const float*)d_in[7];
    const float* b_upd   = (const float*)d_in[8];
    const float* W_val   = (const float*)d_in[9];
    const float* b_val   = (const float*)d_in[10];
    const float* W_pol   = (const float*)d_in[11];
    const float* b_pol   = (const float*)d_in[12];
    float* out = (float*)d_out;

    const int EB = (N_EDGES + 255) / 256;

    k_init<<<PBLOCKS, 256>>>(edge_index, node_feats, W_embed, b_embed, W_msg, b_msg);
    k_convert<<<EB, 256>>>(edge_index);
    k_scan<<<1, 1024>>>();
    k_fill<<<EB, 256>>>(edge_index);

    for (int it = 0; it < MP_ITERS; it++) {
        k_aggupd<<<PBLOCKS, 256>>>(W_upd, b_upd, W_msg, b_msg,
                                   it & 1, it == MP_ITERS - 1 ? 1 : 0);
    }

    k_partial<<<256, 256>>>();
    k_final<<<1, 1024>>>(actionable, W_val, b_val, W_pol, b_pol, out);
}

// round 4
// speedup vs baseline: 1.4058x; 1.1424x over previous
#include <cuda_runtime.h>
#include <cuda_bf16.h>
#include <cuda_fp16.h>
#include <cstdint>

#define N_NODES 100000
#define N_EDGES 3200000
#define EMB 32
#define NFEAT 128
#define N_ACT 1024
#define MP_ITERS 5
#define FULL 0xffffffffu
#define PBLOCKS 1216
#define SCAN_B ((N_NODES + 1023) / 1024)   // 98

// ---------------- device scratch (static, no allocs) ----------------
__device__ int    g_is64;
__device__ int    g_csr[N_EDGES];
__device__ int    g_deg[N_NODES];
__device__ int    g_rowstart[N_NODES + 1];
__device__ int    g_fill[N_NODES];
__device__ int    g_bsum[SCAN_B];
__device__ int    g_boff[SCAN_B];
__device__ float  g_x[N_NODES * EMB];
__device__ __half g_m[2][N_NODES * EMB];
__device__ float  g_part[256 * EMB];

__device__ __forceinline__ float lrelu(float v) { return v > 0.f ? v : 0.01f * v; }
__device__ __forceinline__ float4 lrelu4(float4 v) {
    return make_float4(lrelu(v.x), lrelu(v.y), lrelu(v.z), lrelu(v.w));
}
__device__ __forceinline__ void add4(float4& a, const float4& b) {
    a.x += b.x; a.y += b.y; a.z += b.z; a.w += b.w;
}
__device__ __forceinline__ void addh4(float4& a, uint2 v) {
    float2 f0 = __half22float2(*(const __half2*)&v.x);
    float2 f1 = __half22float2(*(const __half2*)&v.y);
    a.x += f0.x; a.y += f0.y; a.z += f1.x; a.w += f1.y;
}
__device__ __forceinline__ void xorred4(float4& a) {
    a.x += __shfl_xor_sync(FULL, a.x, 8);
    a.y += __shfl_xor_sync(FULL, a.y, 8);
    a.z += __shfl_xor_sync(FULL, a.z, 8);
    a.w += __shfl_xor_sync(FULL, a.w, 8);
    a.x += __shfl_xor_sync(FULL, a.x, 16);
    a.y += __shfl_xor_sync(FULL, a.y, 16);
    a.z += __shfl_xor_sync(FULL, a.z, 16);
    a.w += __shfl_xor_sync(FULL, a.w, 16);
}
#define PICK4(v, c) ((c) == 0 ? (v).x : (c) == 1 ? (v).y : (c) == 2 ? (v).z : (v).w)

// ---------------- K_init: zero deg + probe dtype + embed + first message ----------------
__global__ __launch_bounds__(256) void k_init(const void* __restrict__ edge,
                                              const float* __restrict__ nf,
                                              const float* __restrict__ We,
                                              const float* __restrict__ be,
                                              const float* __restrict__ Wm,
                                              const float* __restrict__ bm) {
    for (int i = blockIdx.x * 256 + threadIdx.x; i < N_NODES; i += gridDim.x * 256)
        g_deg[i] = 0;

    if (blockIdx.x == 0) {
        const long long* p = (const long long*)edge;
        int bad = 0;
        for (int i = threadIdx.x; i < 1024; i += 256) {
            long long v = p[i];
            if (v < 0 || v >= N_NODES) bad = 1;
        }
        bad = __syncthreads_or(bad);
        if (threadIdx.x == 0) g_is64 = bad ? 0 : 1;
    }

    __shared__ float sWe[NFEAT * EMB];
    __shared__ float sWm[EMB * EMB];
    __shared__ float sbe[EMB], sbm[EMB];
    for (int i = threadIdx.x; i < NFEAT * EMB; i += 256) sWe[i] = We[i];
    for (int i = threadIdx.x; i < EMB * EMB; i += 256) sWm[i] = Wm[i];
    if (threadIdx.x < EMB) { sbe[threadIdx.x] = be[threadIdx.x]; sbm[threadIdx.x] = bm[threadIdx.x]; }
    __syncthreads();

    const int lane = threadIdx.x & 31;
    const int warps = gridDim.x * 8;
    for (int n = (blockIdx.x * 256 + threadIdx.x) >> 5; n < N_NODES; n += warps) {
        const float4* row = (const float4*)(nf + (size_t)n * NFEAT);
        float4 mine = row[lane];
        float acc = sbe[lane];
        #pragma unroll
        for (int sl = 0; sl < 32; sl++) {
            float a0 = __shfl_sync(FULL, mine.x, sl);
            float a1 = __shfl_sync(FULL, mine.y, sl);
            float a2 = __shfl_sync(FULL, mine.z, sl);
            float a3 = __shfl_sync(FULL, mine.w, sl);
            int k = sl * 4;
            acc += a0 * sWe[(k + 0) * EMB + lane];
            acc += a1 * sWe[(k + 1) * EMB + lane];
            acc += a2 * sWe[(k + 2) * EMB + lane];
            acc += a3 * sWe[(k + 3) * EMB + lane];
        }
        float x = lrelu(acc);
        g_x[n * EMB + lane] = x;

        float macc = sbm[lane];
        #pragma unroll
        for (int k = 0; k < EMB; k++) {
            float xk = __shfl_sync(FULL, x, k);
            macc += xk * sWm[k * EMB + lane];
        }
        g_m[0][n * EMB + lane] = __float2half_rn(lrelu(macc));
    }
}

// ---------------- K1: degree histogram ----------------
__global__ void k_convert(const void* edge) {
    int e = blockIdx.x * blockDim.x + threadIdx.x;
    if (e >= N_EDGES) return;
    int d;
    if (g_is64) d = (int)((const long long*)edge)[N_EDGES + e];
    else        d = ((const int*)edge)[N_EDGES + e];
    atomicAdd(&g_deg[d], 1);
}

// ---------------- parallel scan: A (block sums), B (scan sums), C (block scan + offset) ----
__global__ __launch_bounds__(1024) void k_scanA() {
    __shared__ int ws[32];
    int i = blockIdx.x * 1024 + threadIdx.x;
    int v = (i < N_NODES) ? g_deg[i] : 0;
    int lane = threadIdx.x & 31, w = threadIdx.x >> 5;
    #pragma unroll
    for (int o = 16; o > 0; o >>= 1) v += __shfl_xor_sync(FULL, v, o);
    if (lane == 0) ws[w] = v;
    __syncthreads();
    if (threadIdx.x < 32) {
        int t = ws[threadIdx.x];
        #pragma unroll
        for (int o = 16; o > 0; o >>= 1) t += __shfl_xor_sync(FULL, t, o);
        if (threadIdx.x == 0) g_bsum[blockIdx.x] = t;
    }
}

__global__ void k_scanB() {
    __shared__ int ws[4];
    int tid = threadIdx.x;            // 128 threads
    int lane = tid & 31, w = tid >> 5;
    int v = (tid < SCAN_B) ? g_bsum[tid] : 0;
    int x = v;
    #pragma unroll
    for (int o = 1; o < 32; o <<= 1) {
        int t = __shfl_up_sync(FULL, x, o);
        if (lane >= o) x += t;
    }
    if (lane == 31) ws[w] = x;
    __syncthreads();
    if (tid == 0) {
        int c = 0;
        #pragma unroll
        for (int i = 0; i < 4; i++) { int t = ws[i]; ws[i] = c; c += t; }
    }
    __syncthreads();
    int excl = x - v + ws[w];
    if (tid < SCAN_B) g_boff[tid] = excl;
    if (tid == 0) g_rowstart[N_NODES] = N_EDGES;
}

__global__ __launch_bounds__(1024) void k_scanC() {
    __shared__ int ws[32];
    int i = blockIdx.x * 1024 + threadIdx.x;
    int v = (i < N_NODES) ? g_deg[i] : 0;
    int lane = threadIdx.x & 31, w = threadIdx.x >> 5;
    int x = v;
    #pragma unroll
    for (int o = 1; o < 32; o <<= 1) {
        int t = __shfl_up_sync(FULL, x, o);
        if (lane >= o) x += t;
    }
    if (lane == 31) ws[w] = x;
    __syncthreads();
    if (threadIdx.x < 32) {
        int t = ws[threadIdx.x];
        #pragma unroll
        for (int o = 1; o < 32; o <<= 1) {
            int u = __shfl_up_sync(FULL, t, o);
            if (threadIdx.x >= o) t += u;
        }
        ws[threadIdx.x] = t;
    }
    __syncthreads();
    int excl = x - v + (w ? ws[w - 1] : 0) + g_boff[blockIdx.x];
    if (i < N_NODES) { g_rowstart[i] = excl; g_fill[i] = excl; }
}

// ---------------- K3: fill CSR ----------------
__global__ void k_fill(const void* edge) {
    int e = blockIdx.x * blockDim.x + threadIdx.x;
    if (e >= N_EDGES) return;
    int s, d;
    if (g_is64) {
        const long long* p = (const long long*)edge;
        s = (int)p[e];
        d = (int)p[N_EDGES + e];
    } else {
        const int* p = (const int*)edge;
        s = p[e];
        d = p[N_EDGES + e];
    }
    int pos = atomicAdd(&g_fill[d], 1);
    g_csr[pos] = s;
}

// ---------------- K5: aggregate + update + next message, fused, persistent ----------------
__global__ __launch_bounds__(256) void k_aggupd(const float* __restrict__ Wu,
                                                const float* __restrict__ bu,
                                                const float* __restrict__ Wm,
                                                const float* __restrict__ bm,
                                                int pin, int last) {
    __shared__ float4 sWu[2 * EMB * 8];
    __shared__ float4 sWm[EMB * 8];
    __shared__ float4 sbu[8], sbm[8];
    for (int i = threadIdx.x; i < 2 * EMB * 8; i += 256) sWu[i] = ((const float4*)Wu)[i];
    for (int i = threadIdx.x; i < EMB * 8; i += 256) sWm[i] = ((const float4*)Wm)[i];
    if (threadIdx.x < 8)  sbu[threadIdx.x] = ((const float4*)bu)[threadIdx.x];
    else if (threadIdx.x < 16) sbm[threadIdx.x - 8] = ((const float4*)bm)[threadIdx.x - 8];
    __syncthreads();

    const int lane = threadIdx.x & 31;
    const int g = lane >> 3;
    const int sub = lane & 7;
    const int warps = gridDim.x * 8;

    const uint2* __restrict__ mbuf = (const uint2*)g_m[pin];   // 8B = 4 fp16 feats
    uint2* __restrict__ mout = (uint2*)g_m[pin ^ 1];

    for (int n = (blockIdx.x * 256 + threadIdx.x) >> 5; n < N_NODES; n += warps) {
        const int beg = g_rowstart[n];
        const int end = g_rowstart[n + 1];

        float4 a0 = make_float4(0.f, 0.f, 0.f, 0.f);
        float4 a1 = make_float4(0.f, 0.f, 0.f, 0.f);
        float4 a2 = make_float4(0.f, 0.f, 0.f, 0.f);
        float4 a3 = make_float4(0.f, 0.f, 0.f, 0.f);
        for (int base = beg; base < end; base += 16) {
            const int e = base + g;
            int i0 = (e      < end) ? g_csr[e]      : -1;
            int i1 = (e + 4  < end) ? g_csr[e + 4]  : -1;
            int i2 = (e + 8  < end) ? g_csr[e + 8]  : -1;
            int i3 = (e + 12 < end) ? g_csr[e + 12] : -1;
            if (i0 >= 0) addh4(a0, mbuf[i0 * 8 + sub]);
            if (i1 >= 0) addh4(a1, mbuf[i1 * 8 + sub]);
            if (i2 >= 0) addh4(a2, mbuf[i2 * 8 + sub]);
            if (i3 >= 0) addh4(a3, mbuf[i3 * 8 + sub]);
        }
        add4(a0, a1); add4(a2, a3); add4(a0, a2);
        xorred4(a0);

        const float xown = g_x[n * EMB + lane];
        float4 outv = make_float4(0.f, 0.f, 0.f, 0.f);
        #pragma unroll
        for (int j = 0; j < 8; j++) {
            const int k = (lane & 24) + j;
            const float xk = __shfl_sync(FULL, xown, k);
            const int s = ((lane & 24) >> 2) + (j >> 2);
            const float ac = PICK4(a0, j & 3);
            const float ak = __shfl_sync(FULL, ac, s);
            const float4 w1 = sWu[k * 8 + sub];
            const float4 w2 = sWu[(k + EMB) * 8 + sub];
            outv.x += xk * w1.x + ak * w2.x;
            outv.y += xk * w1.y + ak * w2.y;
            outv.z += xk * w1.z + ak * w2.z;
            outv.w += xk * w1.w + ak * w2.w;
        }
        xorred4(outv);
        {
            const float4 b = sbu[sub];
            outv.x += b.x; outv.y += b.y; outv.z += b.z; outv.w += b.w;
            outv = lrelu4(outv);
        }
        if (lane < 8) ((float4*)(g_x + n * EMB))[lane] = outv;

        if (!last) {
            float4 macc = make_float4(0.f, 0.f, 0.f, 0.f);
            #pragma unroll
            for (int j = 0; j < 8; j++) {
                const int k = (lane & 24) + j;
                const int s = ((lane & 24) >> 2) + (j >> 2);
                const float xc = PICK4(outv, j & 3);
                const float xk = __shfl_sync(FULL, xc, s);
                const float4 w = sWm[k * 8 + sub];
                macc.x += xk * w.x;
                macc.y += xk * w.y;
                macc.z += xk * w.z;
                macc.w += xk * w.w;
            }
            xorred4(macc);
            const float4 b = sbm[sub];
            macc.x += b.x; macc.y += b.y; macc.z += b.z; macc.w += b.w;
            macc = lrelu4(macc);
            if (lane < 8) {
                __half2 p0 = __floats2half2_rn(macc.x, macc.y);
                __half2 p1 = __floats2half2_rn(macc.z, macc.w);
                uint2 v;
                v.x = *(const unsigned*)&p0;
                v.y = *(const unsigned*)&p1;
                mout[n * 8 + lane] = v;
            }
        }
    }
}

// ---------------- K7: partial column sums for mean (deterministic) ----------------
__global__ __launch_bounds__(256) void k_partial() {
    __shared__ float red[8][EMB];
    int lane = threadIdx.x & 31;
    int w = threadIdx.x >> 5;
    float s = 0.f;
    for (int n = blockIdx.x * 8 + w; n < N_NODES; n += 256 * 8)
        s += g_x[n * EMB + lane];
    red[w][lane] = s;
    __syncthreads();
    if (w == 0) {
        float t = red[0][lane];
        #pragma unroll
        for (int i = 1; i < 8; i++) t += red[i][lane];
        g_part[blockIdx.x * EMB + lane] = t;
    }
}

// ---------------- K8: value + actionable logits + softmax ----------------
__global__ __launch_bounds__(1024) void k_final(const void* __restrict__ act,
                                                const float* __restrict__ Wv,
                                                const float* __restrict__ bv,
                                                const float* __restrict__ Wp,
                                                const float* __restrict__ bp,
                                                float* __restrict__ out) {
    __shared__ float sh[1024];
    __shared__ float xg[EMB];
    int tid = threadIdx.x;

    if (tid < EMB) {
        float s = 0.f;
        for (int p = 0; p < 256; p++) s += g_part[p * EMB + tid];
        xg[tid] = s / (float)N_NODES;
    }
    __syncthreads();
    if (tid == 0) {
        float v = bv[0];
        #pragma unroll
        for (int k = 0; k < EMB; k++) v += xg[k] * Wv[k];
        out[0] = v;
    }

    int node;
    if (g_is64) node = (int)((const long long*)act)[tid];
    else        node = ((const int*)act)[tid];

    float l = bp[0];
    #pragma unroll
    for (int k = 0; k < EMB; k++) l += g_x[node * EMB + k] * Wp[k];

    sh[tid] = l;
    __syncthreads();
    for (int s2 = 512; s2 > 0; s2 >>= 1) {
        if (tid < s2) sh[tid] = fmaxf(sh[tid], sh[tid + s2]);
        __syncthreads();
    }
    float mx = sh[0];
    __syncthreads();
    float e = expf(l - mx);
    sh[tid] = e;
    __syncthreads();
    for (int s2 = 512; s2 > 0; s2 >>= 1) {
        if (tid < s2) sh[tid] += sh[tid + s2];
        __syncthreads();
    }
    out[1 + tid] = e / sh[0];
}

// ---------------- launch ----------------
extern "C" void kernel_launch(void* const* d_in, const int* in_sizes, int n_in,
                              void* d_out, int out_size) {
    const float* node_feats = (const float*)d_in[0];
    const void*  edge_index = d_in[1];
    const void*  actionable = d_in[2];
    const float* W_embed = (const float*)d_in[3];
    const float* b_embed = (const float*)d_in[4];
    const float* W_msg   = (const float*)d_in[5];
    const float* b_msg   = (const float*)d_in[6];
    const float* W_upd   = (const float*)d_in[7];
    const float* b_upd   = (const float*)d_in[8];
    const float* W_val   = (const float*)d_in[9];
    const float* b_val   = (const float*)d_in[10];
    const float* W_pol   = (const float*)d_in[11];
    const float* b_pol   = (const float*)d_in[12];
    float* out = (float*)d_out;

    const int EB = (N_EDGES + 255) / 256;

    k_init<<<PBLOCKS, 256>>>(edge_index, node_feats, W_embed, b_embed, W_msg, b_msg);
    k_convert<<<EB, 256>>>(edge_index);
    k_scanA<<<SCAN_B, 1024>>>();
    k_scanB<<<1, 128>>>();
    k_scanC<<<SCAN_B, 1024>>>();
    k_fill<<<EB, 256>>>(edge_index);

    for (int it = 0; it < MP_ITERS; it++) {
        k_aggupd<<<PBLOCKS, 256>>>(W_upd, b_upd, W_msg, b_msg,
                                   it & 1, it == MP_ITERS - 1 ? 1 : 0);
    }

    k_partial<<<256, 256>>>();
    k_final<<<1, 1024>>>(actionable, W_val, b_val, W_pol, b_pol, out);
}